// round 4
// baseline (speedup 1.0000x reference)
#include <cuda_runtime.h>
#include <math.h>
#include <stdint.h>

// Problem constants
constexpr int B  = 4;
constexpr int T  = 2048;
constexpr int D  = 768;
constexpr int H  = 12;
constexpr int HD = 64;
constexpr int BT = B * T;          // 8192
constexpr int NQKV = 3 * D;        // 2304
constexpr float EPS  = 1e-4f;
constexpr float GAIN = 1.8402f;

constexpr int PAD  = 36;           // GEMM k-chunk stride: (4g+c) mod 32 unique
constexpr int APAD = 68;           // attention 64-wide tile stride (4 mod 32)
constexpr int KC   = 32;           // GEMM k-chunk
constexpr int NC   = D / KC;       // 24 chunks
constexpr int NCT  = T / 64;       // 32 attention KV chunks

// SMEM stage sizes (uint32 units)
constexpr int GA_SZ = 128 * PAD;           // 4608
constexpr int GSTAGE = 2 * GA_SZ;          // A + B per stage = 9216
constexpr int ASTAGE = 2 * 64 * APAD;      // K + V per stage = 8704
constexpr int GEMM_SMEM = 2 * GSTAGE * 4;  // 73728 B
constexpr int ATTN_SMEM = 2 * ASTAGE * 4;  // 69632 B

// Scratch (allocation-free rule: __device__ globals). All tf32 bit patterns.
__device__ uint32_t g_xt[BT * D];
__device__ uint32_t g_wn_qkv[NQKV * D];
__device__ uint32_t g_wn_out[D * D];
__device__ uint32_t g_Q[B * H * T * HD];
__device__ uint32_t g_K[B * H * T * HD];
__device__ uint32_t g_V[B * H * T * HD];
__device__ uint32_t g_att[BT * D];
__device__ float    g_mag[BT];

__device__ __forceinline__ uint32_t tf32(float x) {
    uint32_t u; asm("cvt.rna.tf32.f32 %0, %1;" : "=r"(u) : "f"(x)); return u;
}
__device__ __forceinline__ void mma8(float c[4], const uint32_t a[4], const uint32_t b[2]) {
    asm volatile(
        "mma.sync.aligned.m16n8k8.row.col.f32.tf32.tf32.f32 "
        "{%0,%1,%2,%3}, {%4,%5,%6,%7}, {%8,%9}, {%0,%1,%2,%3};"
        : "+f"(c[0]), "+f"(c[1]), "+f"(c[2]), "+f"(c[3])
        : "r"(a[0]), "r"(a[1]), "r"(a[2]), "r"(a[3]), "r"(b[0]), "r"(b[1]));
}
__device__ __forceinline__ uint32_t saddr(const void* p) {
    return (uint32_t)__cvta_generic_to_shared(p);
}
__device__ __forceinline__ void cp16(uint32_t s, const void* g) {
    asm volatile("cp.async.cg.shared.global [%0], [%1], 16;" :: "r"(s), "l"(g));
}
__device__ __forceinline__ void cp_commit() {
    asm volatile("cp.async.commit_group;" ::: "memory");
}
template <int N>
__device__ __forceinline__ void cp_wait() {
    asm volatile("cp.async.wait_group %0;" :: "n"(N) : "memory");
}

// ---------------------------------------------------------------------------
// Kernel 1: weight row-norm -> tf32; x -> tf32 copy + per-token magnitude.
// ---------------------------------------------------------------------------
__global__ void __launch_bounds__(256) prep_kernel(const float* __restrict__ x,
                                                   const float* __restrict__ qkv_w,
                                                   const float* __restrict__ out_w) {
    const int r = blockIdx.x;
    const float* src;
    uint32_t* dst;
    float* magdst = nullptr;
    bool donorm = true;
    if (r < NQKV) {
        src = qkv_w + (size_t)r * D;  dst = g_wn_qkv + (size_t)r * D;
    } else if (r < NQKV + D) {
        src = out_w + (size_t)(r - NQKV) * D;  dst = g_wn_out + (size_t)(r - NQKV) * D;
    } else {
        const int tr = r - (NQKV + D);
        src = x + (size_t)tr * D;  dst = g_xt + (size_t)tr * D;
        magdst = g_mag + tr;  donorm = false;
    }
    const int tid = threadIdx.x;
    float v[3];
    float s = 0.f;
#pragma unroll
    for (int i = 0; i < 3; i++) { v[i] = src[tid + i * 256]; s += v[i] * v[i]; }
#pragma unroll
    for (int o = 16; o > 0; o >>= 1) s += __shfl_xor_sync(0xffffffffu, s, o);
    __shared__ float red[8];
    __shared__ float stot;
    if ((tid & 31) == 0) red[tid >> 5] = s;
    __syncthreads();
    if (tid == 0) {
        float t = red[0];
#pragma unroll
        for (int i = 1; i < 8; i++) t += red[i];
        stot = t;
    }
    __syncthreads();
    const float tot = stot;
    if (donorm) {
        const float inv = 1.0f / (sqrtf(tot) + EPS);
#pragma unroll
        for (int i = 0; i < 3; i++) dst[tid + i * 256] = tf32(v[i] * inv);
    } else {
#pragma unroll
        for (int i = 0; i < 3; i++) dst[tid + i * 256] = tf32(v[i]);
        if (tid == 0) magdst[0] = sqrtf(tot) * (1.0f / sqrtf((float)D));
    }
}

// ---------------------------------------------------------------------------
// tf32 GEMM core v2: C[128 x 128] = A[m0..][:] * W[n0..][:]^T
// 8 warps (4m x 2n), warp tile 32x64. cp.async 2-stage pipeline.
// ---------------------------------------------------------------------------
__device__ __forceinline__ void gemm_core(const uint32_t* __restrict__ A,
                                          const uint32_t* __restrict__ W,
                                          int m0, int n0, uint32_t* sm,
                                          float (&acc)[2][8][4], int tid) {
    const int lane = tid & 31, warp = tid >> 5;
    const int wm = warp >> 1, wn = warp & 1;
    const int g = lane >> 2, c = lane & 3;
    const uint32_t* Ab = A + (size_t)m0 * D;
    const uint32_t* Wb = W + (size_t)n0 * D;
    const int sr = tid >> 3, scol = (tid & 7) * 4;

    const uint32_t smA0 = saddr(sm);
    // stage s: A at s*GSTAGE, B at s*GSTAGE + GA_SZ (uint32 units)
    auto load_chunk = [&](int s, int k0) {
        const uint32_t baseA = smA0 + (uint32_t)(s * GSTAGE) * 4;
        const uint32_t baseB = baseA + (uint32_t)GA_SZ * 4;
#pragma unroll
        for (int i = 0; i < 4; i++) {
            const int row = sr + i * 32;
            cp16(baseA + (uint32_t)(row * PAD + scol) * 4, Ab + (size_t)row * D + k0 + scol);
        }
#pragma unroll
        for (int i = 0; i < 4; i++) {
            const int row = sr + i * 32;
            cp16(baseB + (uint32_t)(row * PAD + scol) * 4, Wb + (size_t)row * D + k0 + scol);
        }
    };

    load_chunk(0, 0);
    cp_commit();
    for (int i = 0; i < NC; i++) {
        if (i + 1 < NC) {
            load_chunk((i + 1) & 1, (i + 1) * KC);
            cp_commit();
            cp_wait<1>();
        } else {
            cp_wait<0>();
        }
        __syncthreads();
        const uint32_t* As = sm + (i & 1) * GSTAGE;
        const uint32_t* Bs = As + GA_SZ;
#pragma unroll
        for (int ks = 0; ks < 4; ks++) {
            const int kk = ks * 8;
            uint32_t af[2][4], bf[8][2];
#pragma unroll
            for (int mt = 0; mt < 2; mt++) {
                const uint32_t* p = &As[(wm * 32 + mt * 16 + g) * PAD + kk + c];
                af[mt][0] = p[0];        af[mt][2] = p[4];
                af[mt][1] = p[8 * PAD];  af[mt][3] = p[8 * PAD + 4];
            }
#pragma unroll
            for (int nt = 0; nt < 8; nt++) {
                const uint32_t* p = &Bs[(wn * 64 + nt * 8 + g) * PAD + kk + c];
                bf[nt][0] = p[0]; bf[nt][1] = p[4];
            }
#pragma unroll
            for (int mt = 0; mt < 2; mt++)
#pragma unroll
                for (int nt = 0; nt < 8; nt++) mma8(acc[mt][nt], af[mt], bf[nt]);
        }
        __syncthreads();
    }
}

// ---------------------------------------------------------------------------
// Kernel 2: qkv GEMM + warp-local per-head q/k RMS-normalize + tf32 scatter.
// grid: (2304/128, 8192/128). Each warp's 64-wide n-extent == one head.
// ---------------------------------------------------------------------------
__global__ void __launch_bounds__(256) qkv_mm() {
    extern __shared__ uint32_t sm[];
    const int n0 = blockIdx.x * 128, m0 = blockIdx.y * 128;
    const int tid = threadIdx.x, lane = tid & 31, warp = tid >> 5;
    const int wm = warp >> 1, wn = warp & 1, g = lane >> 2, c = lane & 3;

    float acc[2][8][4] = {};
    gemm_core(g_xt, g_wn_qkv, m0, n0, sm, acc, tid);

    const int which = n0 / D;                      // 0=q 1=k 2=v
    const int head = (n0 % D) / HD + wn;           // warp owns one full head
    const int b = m0 / T;
    uint32_t* dstb = (which == 0) ? g_Q : (which == 1) ? g_K : g_V;

#pragma unroll
    for (int mt = 0; mt < 2; mt++) {
        float sc[2] = {1.f, 1.f};
        if (which < 2) {
            float s0 = 0.f, s1 = 0.f;
#pragma unroll
            for (int nt = 0; nt < 8; nt++) {
                s0 += acc[mt][nt][0] * acc[mt][nt][0] + acc[mt][nt][1] * acc[mt][nt][1];
                s1 += acc[mt][nt][2] * acc[mt][nt][2] + acc[mt][nt][3] * acc[mt][nt][3];
            }
            s0 += __shfl_xor_sync(~0u, s0, 1); s0 += __shfl_xor_sync(~0u, s0, 2);
            s1 += __shfl_xor_sync(~0u, s1, 1); s1 += __shfl_xor_sync(~0u, s1, 2);
            sc[0] = 8.0f / (sqrtf(s0) + EPS);      // sqrt(HD)=8
            sc[1] = 8.0f / (sqrtf(s1) + EPS);
        }
#pragma unroll
        for (int rr = 0; rr < 2; rr++) {
            const int m = m0 + wm * 32 + mt * 16 + g + rr * 8;
            const int t = m & (T - 1);
            uint32_t* dp = dstb + (((size_t)(b * H + head)) * T + t) * HD;
#pragma unroll
            for (int nt = 0; nt < 8; nt++) {
                const int col = nt * 8 + 2 * c;
                uint2 v = make_uint2(tf32(acc[mt][nt][rr * 2] * sc[rr]),
                                     tf32(acc[mt][nt][rr * 2 + 1] * sc[rr]));
                *(uint2*)&dp[col] = v;
            }
        }
    }
}

// ---------------------------------------------------------------------------
// Kernel 3: fused sigmoid attention, cp.async 2-stage K/V pipeline.
// Block: 128 q-rows, 8 warps (16 rows x 64 cols). Q frags in registers.
// grid: (T/128, H, B)
// ---------------------------------------------------------------------------
__global__ void __launch_bounds__(256) attn_mma() {
    extern __shared__ uint32_t sm[];
    const int tid = threadIdx.x, lane = tid & 31, warp = tid >> 5;
    const int g = lane >> 2, c = lane & 3;
    const int q0 = blockIdx.x * 128;
    const int h = blockIdx.y, b = blockIdx.z;
    const size_t bh = ((size_t)(b * H + h)) * T;

    // Q fragments (16 rows x 64 k) persistent in registers
    uint32_t qf[8][4];
    {
        const uint32_t* Qg = g_Q + (bh + q0 + warp * 16) * HD;
#pragma unroll
        for (int kt = 0; kt < 8; kt++) {
            qf[kt][0] = Qg[(size_t)g * HD + kt * 8 + c];
            qf[kt][1] = Qg[(size_t)(g + 8) * HD + kt * 8 + c];
            qf[kt][2] = Qg[(size_t)g * HD + kt * 8 + c + 4];
            qf[kt][3] = Qg[(size_t)(g + 8) * HD + kt * 8 + c + 4];
        }
    }

    const uint32_t sm0 = saddr(sm);
    const int sr = tid >> 4, scol = (tid & 15) * 4;
    auto load_kv = [&](int s, int s0) {
        const uint32_t* Kg = g_K + (bh + s0) * HD;
        const uint32_t* Vg = g_V + (bh + s0) * HD;
        const uint32_t baseK = sm0 + (uint32_t)(s * ASTAGE) * 4;
        const uint32_t baseV = baseK + (uint32_t)(64 * APAD) * 4;
#pragma unroll
        for (int i = 0; i < 4; i++) {
            const int row = sr + i * 16;
            cp16(baseK + (uint32_t)(row * APAD + scol) * 4, Kg + (size_t)row * HD + scol);
            cp16(baseV + (uint32_t)(row * APAD + scol) * 4, Vg + (size_t)row * HD + scol);
        }
    };

    float oacc[8][4] = {};
    const int src0 = (lane & 28) | (c >> 1);
    const int src1 = src0 + 2;
    const bool odd = c & 1;

    load_kv(0, 0);
    cp_commit();
    for (int i = 0; i < NCT; i++) {
        if (i + 1 < NCT) {
            load_kv((i + 1) & 1, (i + 1) * 64);
            cp_commit();
            cp_wait<1>();
        } else {
            cp_wait<0>();
        }
        __syncthreads();
        const uint32_t* Ks = sm + (i & 1) * ASTAGE;
        const uint32_t* Vs = Ks + 64 * APAD;

        // S = Q K^T  (16 x 64 per warp)
        float sacc[8][4] = {};
#pragma unroll
        for (int ks = 0; ks < 8; ks++) {
            uint32_t bf[8][2];
#pragma unroll
            for (int nt = 0; nt < 8; nt++) {
                const uint32_t* p = &Ks[(nt * 8 + g) * APAD + ks * 8 + c];
                bf[nt][0] = p[0]; bf[nt][1] = p[4];
            }
#pragma unroll
            for (int nt = 0; nt < 8; nt++) mma8(sacc[nt], qf[ks], bf[nt]);
        }

        // sigmoid(S/8)
#pragma unroll
        for (int nt = 0; nt < 8; nt++)
#pragma unroll
            for (int j = 0; j < 4; j++)
                sacc[nt][j] = 1.0f / (1.0f + __expf(-0.125f * sacc[nt][j]));

        // O += P V  (C-frag -> A-frag via shuffles)
#pragma unroll
        for (int kt = 0; kt < 8; kt++) {
            uint32_t af[4];
            float w0 = __shfl_sync(~0u, sacc[kt][0], src0);
            float w1 = __shfl_sync(~0u, sacc[kt][1], src0);
            af[0] = tf32(odd ? w1 : w0);
            float w2 = __shfl_sync(~0u, sacc[kt][2], src0);
            float w3 = __shfl_sync(~0u, sacc[kt][3], src0);
            af[1] = tf32(odd ? w3 : w2);
            float x0 = __shfl_sync(~0u, sacc[kt][0], src1);
            float x1 = __shfl_sync(~0u, sacc[kt][1], src1);
            af[2] = tf32(odd ? x1 : x0);
            float x2 = __shfl_sync(~0u, sacc[kt][2], src1);
            float x3 = __shfl_sync(~0u, sacc[kt][3], src1);
            af[3] = tf32(odd ? x3 : x2);
#pragma unroll
            for (int nt = 0; nt < 8; nt++) {
                uint32_t bf2[2];
                const uint32_t* vp = &Vs[(kt * 8 + c) * APAD + nt * 8 + g];
                bf2[0] = vp[0]; bf2[1] = vp[4 * APAD];
                mma8(oacc[nt], af, bf2);
            }
        }
        __syncthreads();
    }

    // Epilogue: out = mag * 8*cst*acc / (cst*||acc|| + eps), stored tf32
    const float cst = GAIN * rsqrtf((float)T);
#pragma unroll
    for (int rr = 0; rr < 2; rr++) {
        float s = 0.f;
#pragma unroll
        for (int nt = 0; nt < 8; nt++)
            s += oacc[nt][rr * 2] * oacc[nt][rr * 2] + oacc[nt][rr * 2 + 1] * oacc[nt][rr * 2 + 1];
        s += __shfl_xor_sync(~0u, s, 1);
        s += __shfl_xor_sync(~0u, s, 2);
        const int t = q0 + warp * 16 + g + rr * 8;
        const float n = cst * sqrtf(s);
        const float f = 8.0f * cst * g_mag[b * T + t] / (n + EPS);
        uint32_t* dp = g_att + ((size_t)b * T + t) * D + h * HD;
#pragma unroll
        for (int nt = 0; nt < 8; nt++)
            *(uint2*)&dp[nt * 8 + 2 * c] = make_uint2(tf32(oacc[nt][rr * 2] * f),
                                                      tf32(oacc[nt][rr * 2 + 1] * f));
    }
}

// ---------------------------------------------------------------------------
// Kernel 4: out-projection  y = att @ wn_out^T  (fp32 out)
// grid: (768/128, 8192/128)
// ---------------------------------------------------------------------------
__global__ void __launch_bounds__(256) proj_mm(float* __restrict__ out) {
    extern __shared__ uint32_t sm[];
    const int n0 = blockIdx.x * 128, m0 = blockIdx.y * 128;
    const int tid = threadIdx.x, lane = tid & 31, warp = tid >> 5;
    const int wm = warp >> 1, wn = warp & 1, g = lane >> 2, c = lane & 3;

    float acc[2][8][4] = {};
    gemm_core(g_att, g_wn_out, m0, n0, sm, acc, tid);

#pragma unroll
    for (int mt = 0; mt < 2; mt++) {
#pragma unroll
        for (int rr = 0; rr < 2; rr++) {
            const int m = m0 + wm * 32 + mt * 16 + g + rr * 8;
            float* dp = out + (size_t)m * D + n0 + wn * 64;
#pragma unroll
            for (int nt = 0; nt < 8; nt++) {
                const int col = nt * 8 + 2 * c;
                *(float2*)&dp[col] = make_float2(acc[mt][nt][rr * 2],
                                                 acc[mt][nt][rr * 2 + 1]);
            }
        }
    }
}

// ---------------------------------------------------------------------------
extern "C" void kernel_launch(void* const* d_in, const int* in_sizes, int n_in,
                              void* d_out, int out_size) {
    const float* x     = (const float*)d_in[0];
    const float* qkv_w = (const float*)d_in[1];
    const float* out_w = (const float*)d_in[2];

    static bool attr_done = false;
    if (!attr_done) {
        cudaFuncSetAttribute(qkv_mm, cudaFuncAttributeMaxDynamicSharedMemorySize, GEMM_SMEM);
        cudaFuncSetAttribute(proj_mm, cudaFuncAttributeMaxDynamicSharedMemorySize, GEMM_SMEM);
        cudaFuncSetAttribute(attn_mma, cudaFuncAttributeMaxDynamicSharedMemorySize, ATTN_SMEM);
        attr_done = true;
    }

    prep_kernel<<<NQKV + D + BT, 256>>>(x, qkv_w, out_w);
    qkv_mm<<<dim3(NQKV / 128, BT / 128), 256, GEMM_SMEM>>>();
    attn_mma<<<dim3(T / 128, H, B), 256, ATTN_SMEM>>>();
    proj_mm<<<dim3(D / 128, BT / 128), 256, GEMM_SMEM>>>((float*)d_out);
}